// round 14
// baseline (speedup 1.0000x reference)
#include <cuda_runtime.h>
#include <cuda_fp16.h>
#include <cstdint>

#define B_Q   256
#define N_MEM 50000
#define D_DIM 1024
#define NTILE 128
#define KC    128                            // f16 k-elems per super-chunk (2 slabs)
#define NCHUNK (D_DIM / KC)                  // 8
#define NBLK  ((N_MEM + NTILE - 1) / NTILE)  // 391

// SMEM (dynamic): double-buffered; each buffer = 2 slabs of (Q 32KB + M 16KB)
#define SM_Q     0                            // 2 buf x 64KB  = 128KB
#define SM_M     131072                       // 2 buf x 32KB  = 64KB
#define SM_NORM  (SM_M + 65536)               // 128 floats
#define SMEM_TOTAL (SM_NORM + 512)            // ~193KB

__device__ unsigned long long g_best[B_Q];
__device__ int g_sel[B_Q];
__device__ __half g_qh[B_Q * D_DIM];

__device__ __forceinline__ uint32_t smem_u32(const void* p) {
    uint32_t a;
    asm("{ .reg .u64 t; cvta.to.shared.u64 t, %1; cvt.u32.u64 %0, t; }" : "=r"(a) : "l"(p));
    return a;
}
__device__ __forceinline__ unsigned int fkey(float f) {
    unsigned int u = __float_as_uint(f);
    return (u & 0x80000000u) ? ~u : (u | 0x80000000u);
}
#define SW128(off) ((off) ^ (((off) >> 3) & 0x70))

#define LDSM_X4(r0, r1, r2, r3, a) \
    asm volatile("ldmatrix.sync.aligned.m8n8.x4.shared.b16 {%0,%1,%2,%3}, [%4];" \
                 : "=r"(r0), "=r"(r1), "=r"(r2), "=r"(r3) : "r"(a))
#define LDSM_X4_T(r0, r1, r2, r3, a) \
    asm volatile("ldmatrix.sync.aligned.m8n8.x4.trans.shared.b16 {%0,%1,%2,%3}, [%4];" \
                 : "=r"(r0), "=r"(r1), "=r"(r2), "=r"(r3) : "r"(a))
#define MMA_F16(d, a, b0, b1) \
    asm volatile("mma.sync.aligned.m16n8k16.row.col.f16.f16.f16.f16 " \
                 "{%0,%1}, {%2,%3,%4,%5}, {%6,%7}, {%0,%1};" \
                 : "+r"((d)[0]), "+r"((d)[1]) \
                 : "r"((a)[0]), "r"((a)[1]), "r"((a)[2]), "r"((a)[3]), "r"(b0), "r"(b1))
#define CP_ASYNC_16(dst, src) \
    asm volatile("cp.async.cg.shared.global [%0], [%1], 16;" :: "r"(dst), "l"(src) : "memory")
#define CP_ASYNC_COMMIT() asm volatile("cp.async.commit_group;" ::: "memory")
#define CP_ASYNC_WAIT0()  asm volatile("cp.async.wait_group 0;" ::: "memory")

__device__ __forceinline__ uint32_t pack_h2(float x, float y) {
    __half2 h = __floats2half2_rn(x, y);
    return *reinterpret_cast<uint32_t*>(&h);
}

// Q fp32 -> f16 once; reset g_best.
__global__ __launch_bounds__(256) void prep_kernel(const float* __restrict__ Q) {
    int idx = blockIdx.x * 256 + threadIdx.x;
    const float4 v = reinterpret_cast<const float4*>(Q)[idx];
    uint2 w;
    w.x = pack_h2(v.x, v.y);
    w.y = pack_h2(v.z, v.w);
    reinterpret_cast<uint2*>(g_qh)[idx] = w;
    if (blockIdx.x == 0) g_best[threadIdx.x] = 0ull;
}

// f16 GEMM (256q x 128n x 1024k), f16 acc, fused norms + argmax.
// r12 body, super-chunked: 8 syncs/CTA, Q via cp.async, M register-staged.
__global__ __launch_bounds__(512, 1) void simmax_mma(const float* __restrict__ Mptr) {
    extern __shared__ char smem[];
    const uint32_t sb = smem_u32(smem);
    const int tid = threadIdx.x;
    const int l   = tid & 31;
    const int wid = tid >> 5;
    const int wq  = wid >> 2;          // 0..3 : q block of 64
    const int wn  = wid & 3;           // 0..3 : n block of 32
    const int ntile = blockIdx.x * NTILE;

    float* norms = reinterpret_cast<float*>(smem + SM_NORM);

    uint32_t acc[4][4][2];             // f16x2 accumulators (64q x 32n per warp)
#pragma unroll
    for (int mt = 0; mt < 4; mt++)
#pragma unroll
        for (int nt = 0; nt < 4; nt++) {
            acc[mt][nt][0] = 0u;
            acc[mt][nt][1] = 0u;
        }

    // ---- M loader: 4 threads/row; thread covers 32 fp32 (8 float4) per super-chunk
    const int mrow = tid >> 2;
    const int mq4  = tid & 3;          // column quarter (32 floats each)
    const int gn   = ntile + mrow;
    const bool mvalid = (gn < N_MEM);
    const float* msrc = Mptr + (size_t)gn * D_DIM + mq4 * 32;
    const int mslab = mq4 >> 1;        // which 64-k slab this thread's columns fall in
    const int mhalf = mq4 & 1;         // 64B offset within the slab row
    float4 f[8];
    float sumsq = 0.0f;

    // ---- Q via cp.async: per slab 2048 16B segs, 4/thread; 8 issues per super-chunk
    auto issue_q = [&](int c, int slot) {
        const uint32_t qbuf = sb + SM_Q + slot * 65536;
#pragma unroll
        for (int h = 0; h < 2; h++) {
#pragma unroll
            for (int i = 0; i < 4; i++) {
                int s = tid + 512 * i;
                int qrow = s >> 3, qseg = s & 7;
                const void* src = g_qh + (size_t)qrow * D_DIM + c * KC + h * 64 + qseg * 8;
                uint32_t off = (uint32_t)(qrow * 128 + qseg * 16);
                CP_ASYNC_16(qbuf + h * 32768 + SW128(off), src);
            }
        }
        CP_ASYNC_COMMIT();
    };

    // ---- prologue
    issue_q(0, 0);
#pragma unroll
    for (int i = 0; i < 8; i++)
        f[i] = mvalid ? *reinterpret_cast<const float4*>(msrc + i * 4)
                      : make_float4(0.f, 0.f, 0.f, 0.f);

    const int lrow = l & 15;
    const int lhi  = (l >> 4) * 16;

    for (int c = 0; c < NCHUNK; c++) {
        const int slot = c & 1;
        const uint32_t qbuf = (uint32_t)(SM_Q + slot * 65536);
        const uint32_t mbuf = (uint32_t)(SM_M + slot * 32768);

        // ---- STS M(c): fp32 -> f16 + fused sumsq (32 f16 = 4 uint4 stores)
        {
            uint32_t w[16];
#pragma unroll
            for (int i = 0; i < 8; i++) {
                sumsq += f[i].x * f[i].x + f[i].y * f[i].y + f[i].z * f[i].z + f[i].w * f[i].w;
                w[i * 2]     = pack_h2(f[i].x, f[i].y);
                w[i * 2 + 1] = pack_h2(f[i].z, f[i].w);
            }
            uint32_t base = (uint32_t)(mrow * 128 + mhalf * 64);
#pragma unroll
            for (int j = 0; j < 4; j++)
                *reinterpret_cast<uint4*>(smem + mbuf + mslab * 16384 + SW128(base + j * 16))
                    = *reinterpret_cast<uint4*>(&w[j * 4]);
        }
        CP_ASYNC_WAIT0();   // Q(c) landed
        __syncthreads();    // super-chunk c visible; orders compute(c-1) vs buffer reuse

        // ---- prefetch super-chunk c+1 (hidden under compute below)
        if (c + 1 < NCHUNK) {
            issue_q(c + 1, slot ^ 1);
#pragma unroll
            for (int i = 0; i < 8; i++)
                f[i] = mvalid ? *reinterpret_cast<const float4*>(msrc + (c + 1) * KC + i * 4)
                              : make_float4(0.f, 0.f, 0.f, 0.f);
        }

        // ---- compute super-chunk c: 2 slabs x 4 k16 steps
#pragma unroll
        for (int h = 0; h < 2; h++) {
            const uint32_t qb = qbuf + h * 32768;
            const uint32_t mb = mbuf + h * 16384;
#pragma unroll
            for (int ks = 0; ks < 4; ks++) {
                uint32_t b[2][4];
#pragma unroll
                for (int p = 0; p < 2; p++) {
                    uint32_t off = (uint32_t)((wn * 32 + p * 16 + lrow) * 128 + ks * 32 + lhi);
                    LDSM_X4_T(b[p][0], b[p][1], b[p][2], b[p][3], sb + mb + SW128(off));
                }
#pragma unroll
                for (int mt = 0; mt < 4; mt++) {
                    uint32_t a[4];
                    uint32_t off = (uint32_t)((wq * 64 + mt * 16 + lrow) * 128 + ks * 32 + lhi);
                    LDSM_X4(a[0], a[1], a[2], a[3], sb + qb + SW128(off));
#pragma unroll
                    for (int nt = 0; nt < 4; nt++)
                        MMA_F16(acc[mt][nt], a, b[nt >> 1][nt & 1], b[nt >> 1][(nt & 1) + 2]);
                }
            }
        }
        // single sync per super-chunk: next STS/cp.async target the other buffer.
    }

    // ---- row norms (4 threads/row, fp32 exact)
    sumsq += __shfl_xor_sync(0xFFFFFFFFu, sumsq, 1);
    sumsq += __shfl_xor_sync(0xFFFFFFFFu, sumsq, 2);
    if (mq4 == 0) norms[mrow] = rsqrtf(fmaxf(sumsq, 1e-30f));
    __syncthreads();
    const float* invn = norms;

    // ---- epilogue: per-q-row argmax over this CTA's 128 n
#pragma unroll
    for (int mt = 0; mt < 4; mt++) {
#pragma unroll
        for (int sub = 0; sub < 2; sub++) {
            unsigned long long best = 0ull;
#pragma unroll
            for (int nt = 0; nt < 4; nt++) {
                __half2 h = *reinterpret_cast<__half2*>(&acc[mt][nt][sub]);
                float2 fv = __half22float2(h);
#pragma unroll
                for (int cc = 0; cc < 2; cc++) {
                    int nl = wn * 32 + nt * 8 + 2 * (l & 3) + cc;
                    int n = ntile + nl;
                    if (n < N_MEM) {
                        float s = (cc == 0 ? fv.x : fv.y) * invn[nl];
                        unsigned long long key =
                            ((unsigned long long)fkey(s) << 32) |
                            (unsigned long long)(unsigned int)(~(unsigned int)n);
                        if (key > best) best = key;
                    }
                }
            }
            unsigned long long o;
            o = __shfl_xor_sync(0xFFFFFFFFu, best, 1); if (o > best) best = o;
            o = __shfl_xor_sync(0xFFFFFFFFu, best, 2); if (o > best) best = o;
            if ((l & 3) == 0) {
                int q = wq * 64 + mt * 16 + (l >> 2) + sub * 8;
                atomicMax(&g_best[q], best);
            }
        }
    }
}

// Exact fp32 recompute of the winner's cosine sim + threshold.
__global__ __launch_bounds__(256) void finalize_kernel(const float* __restrict__ Q,
                                                       const float* __restrict__ M) {
    __shared__ float sdq[256], sdm[256], sdp[256];
    const int b = blockIdx.x;
    const int tid = threadIdx.x;

    unsigned long long pk = g_best[b];
    int idx = (int)(~(unsigned int)(pk & 0xFFFFFFFFull));

    const float* q = Q + (size_t)b * D_DIM;
    const float* m = M + (size_t)idx * D_DIM;
    float dq = 0.f, dm = 0.f, dp = 0.f;
    for (int k = tid * 4; k < D_DIM; k += 256 * 4) {
        float4 qa = *reinterpret_cast<const float4*>(&q[k]);
        float4 mb = *reinterpret_cast<const float4*>(&m[k]);
        dq += qa.x * qa.x + qa.y * qa.y + qa.z * qa.z + qa.w * qa.w;
        dm += mb.x * mb.x + mb.y * mb.y + mb.z * mb.z + mb.w * mb.w;
        dp += qa.x * mb.x + qa.y * mb.y + qa.z * mb.z + qa.w * mb.w;
    }
    sdq[tid] = dq; sdm[tid] = dm; sdp[tid] = dp;
    __syncthreads();
    for (int s = 128; s > 0; s >>= 1) {
        if (tid < s) {
            sdq[tid] += sdq[tid + s];
            sdm[tid] += sdm[tid + s];
            sdp[tid] += sdp[tid + s];
        }
        __syncthreads();
    }
    if (tid == 0) {
        float sim = sdp[0] / fmaxf(sqrtf(sdq[0]) * sqrtf(sdm[0]), 1e-8f);
        g_sel[b] = (sim > 0.6f) ? idx : -1;
    }
}

__global__ __launch_bounds__(128) void decode_kernel(const float* __restrict__ M,
                                                     const float* __restrict__ W,
                                                     const float* __restrict__ bias,
                                                     float* __restrict__ out) {
    const int b = blockIdx.y;
    const int j = blockIdx.x * 128 + threadIdx.x;
    const int sel = g_sel[b];
    float r = 0.0f;
    if (sel >= 0) {
        const float* e = M + (size_t)sel * D_DIM;
        const float* w = W + (size_t)j * D_DIM;
        float s = 0.0f;
        for (int k = 0; k < D_DIM; k += 4) {
            float4 ev = *reinterpret_cast<const float4*>(&e[k]);
            float4 wv = *reinterpret_cast<const float4*>(&w[k]);
            s += ev.x * wv.x + ev.y * wv.y + ev.z * wv.z + ev.w * wv.w;
        }
        r = s + bias[j];
    }
    out[(size_t)b * D_DIM + j] = r;
}

extern "C" void kernel_launch(void* const* d_in, const int* in_sizes, int n_in,
                              void* d_out, int out_size) {
    const float* Q    = (const float*)d_in[0];
    const float* M    = (const float*)d_in[1];
    const float* W    = (const float*)d_in[2];
    const float* bias = (const float*)d_in[3];
    float* out = (float*)d_out;

    cudaFuncSetAttribute(simmax_mma, cudaFuncAttributeMaxDynamicSharedMemorySize, SMEM_TOTAL);

    prep_kernel<<<B_Q * D_DIM / 4 / 256, 256>>>(Q);
    simmax_mma<<<NBLK, 512, SMEM_TOTAL>>>(M);
    finalize_kernel<<<B_Q, 256>>>(Q, M);
    decode_kernel<<<dim3(D_DIM / 128, B_Q), 128>>>(M, W, bias, out);
}

// round 15
// speedup vs baseline: 1.3459x; 1.3459x over previous
#include <cuda_runtime.h>
#include <cuda_fp16.h>
#include <cstdint>

#define B_Q   256
#define N_MEM 50000
#define D_DIM 1024
#define NTILE 128
#define KC    64                             // f16 elements per chunk (128B row)
#define NCHUNK (D_DIM / KC)                  // 16
#define NBLK  ((N_MEM + NTILE - 1) / NTILE)  // 391

// SMEM (dynamic): double-buffered Q and M
#define SM_Q     0                       // 2 x 32KB (256 rows x 128B)
#define SM_M     65536                   // 2 x 16KB (128 rows x 128B)
#define SM_NORM  (SM_M + 32768)          // 128 floats
#define SMEM_TOTAL (SM_NORM + 512)

__device__ unsigned long long g_best[B_Q];
__device__ __half g_qh[B_Q * D_DIM];

__device__ __forceinline__ uint32_t smem_u32(const void* p) {
    uint32_t a;
    asm("{ .reg .u64 t; cvta.to.shared.u64 t, %1; cvt.u32.u64 %0, t; }" : "=r"(a) : "l"(p));
    return a;
}
__device__ __forceinline__ unsigned int fkey(float f) {
    unsigned int u = __float_as_uint(f);
    return (u & 0x80000000u) ? ~u : (u | 0x80000000u);
}
#define SW128(off) ((off) ^ (((off) >> 3) & 0x70))

#define LDSM_X4(r0, r1, r2, r3, a) \
    asm volatile("ldmatrix.sync.aligned.m8n8.x4.shared.b16 {%0,%1,%2,%3}, [%4];" \
                 : "=r"(r0), "=r"(r1), "=r"(r2), "=r"(r3) : "r"(a))
#define LDSM_X4_T(r0, r1, r2, r3, a) \
    asm volatile("ldmatrix.sync.aligned.m8n8.x4.trans.shared.b16 {%0,%1,%2,%3}, [%4];" \
                 : "=r"(r0), "=r"(r1), "=r"(r2), "=r"(r3) : "r"(a))
#define MMA_F16(d, a, b0, b1) \
    asm volatile("mma.sync.aligned.m16n8k16.row.col.f16.f16.f16.f16 " \
                 "{%0,%1}, {%2,%3,%4,%5}, {%6,%7}, {%0,%1};" \
                 : "+r"((d)[0]), "+r"((d)[1]) \
                 : "r"((a)[0]), "r"((a)[1]), "r"((a)[2]), "r"((a)[3]), "r"(b0), "r"(b1))

__device__ __forceinline__ uint32_t pack_h2(float x, float y) {
    __half2 h = __floats2half2_rn(x, y);
    return *reinterpret_cast<uint32_t*>(&h);
}

// Q fp32 -> f16 once; reset g_best.
__global__ __launch_bounds__(256) void prep_kernel(const float* __restrict__ Q) {
    int idx = blockIdx.x * 256 + threadIdx.x;
    const float4 v = reinterpret_cast<const float4*>(Q)[idx];
    uint2 w;
    w.x = pack_h2(v.x, v.y);
    w.y = pack_h2(v.z, v.w);
    reinterpret_cast<uint2*>(g_qh)[idx] = w;
    if (blockIdx.x == 0) g_best[threadIdx.x] = 0ull;
}

// f16 GEMM (256q x 128n x 1024k), f16 acc, fused norms + argmax.
// r12 body + prefetch-before-barrier: 512 thr, 16 warps (4wq x 4wn),
// 64q x 32n warp tile, double buffer, register staging, 1 sync/chunk.
__global__ __launch_bounds__(512, 1) void simmax_mma(const float* __restrict__ Mptr) {
    extern __shared__ char smem[];
    const uint32_t sb = smem_u32(smem);
    const int tid = threadIdx.x;
    const int l   = tid & 31;
    const int wid = tid >> 5;
    const int wq  = wid >> 2;          // 0..3 : q block of 64
    const int wn  = wid & 3;           // 0..3 : n block of 32
    const int ntile = blockIdx.x * NTILE;

    float* norms = reinterpret_cast<float*>(smem + SM_NORM);

    uint32_t acc[4][4][2];             // f16x2 accumulators (64q x 32n per warp)
#pragma unroll
    for (int mt = 0; mt < 4; mt++)
#pragma unroll
        for (int nt = 0; nt < 4; nt++) {
            acc[mt][nt][0] = 0u;
            acc[mt][nt][1] = 0u;
        }

    // ---- M loader: 4 threads/row, 16 fp32 each
    const int mrow = tid >> 2;
    const int mq4  = tid & 3;
    const int gn   = ntile + mrow;
    const bool mvalid = (gn < N_MEM);
    const float* msrc = Mptr + (size_t)gn * D_DIM + mq4 * 16;
    float4 f[4];
    float sumsq = 0.0f;

    // ---- Q loader: 2048 16B segs/chunk, 4 per thread
    const int s0 = tid, s1 = tid + 512, s2 = tid + 1024, s3 = tid + 1536;
    const int qr[4] = { s0 >> 3, s1 >> 3, s2 >> 3, s3 >> 3 };
    const int qs[4] = { s0 & 7,  s1 & 7,  s2 & 7,  s3 & 7 };
    uint4 qq[4];

    // ---- prologue: prefetch chunk 0
#pragma unroll
    for (int i = 0; i < 4; i++)
        f[i] = mvalid ? *reinterpret_cast<const float4*>(msrc + i * 4)
                      : make_float4(0.f, 0.f, 0.f, 0.f);
#pragma unroll
    for (int i = 0; i < 4; i++)
        qq[i] = *reinterpret_cast<const uint4*>(g_qh + (size_t)qr[i] * D_DIM + qs[i] * 8);

    const int lrow = l & 15;
    const int lhi  = (l >> 4) * 16;

    for (int c = 0; c < NCHUNK; c++) {
        const int slot = c & 1;
        const uint32_t qb = (uint32_t)(SM_Q + slot * 32768);
        const uint32_t mb = (uint32_t)(SM_M + slot * 16384);

        // ---- STS Q(c) from regs
#pragma unroll
        for (int i = 0; i < 4; i++) {
            uint32_t off = (uint32_t)(qr[i] * 128 + qs[i] * 16);
            *reinterpret_cast<uint4*>(smem + qb + SW128(off)) = qq[i];
        }
        // ---- STS M(c): fp32 -> f16 + fused sumsq
        {
            uint32_t w[8];
#pragma unroll
            for (int i = 0; i < 4; i++) {
                sumsq += f[i].x * f[i].x + f[i].y * f[i].y + f[i].z * f[i].z + f[i].w * f[i].w;
                w[i * 2]     = pack_h2(f[i].x, f[i].y);
                w[i * 2 + 1] = pack_h2(f[i].z, f[i].w);
            }
            uint32_t off = (uint32_t)(mrow * 128 + mq4 * 32);
            *reinterpret_cast<uint4*>(smem + mb + SW128(off))      = *reinterpret_cast<uint4*>(&w[0]);
            *reinterpret_cast<uint4*>(smem + mb + SW128(off + 16)) = *reinterpret_cast<uint4*>(&w[4]);
        }

        // ---- prefetch chunk c+1 BEFORE the barrier: regs are private, sources
        //      read-only — early warps put 8 LDGs in flight during barrier wait.
        if (c + 1 < NCHUNK) {
#pragma unroll
            for (int i = 0; i < 4; i++)
                f[i] = mvalid ? *reinterpret_cast<const float4*>(msrc + (c + 1) * KC + i * 4)
                              : make_float4(0.f, 0.f, 0.f, 0.f);
#pragma unroll
            for (int i = 0; i < 4; i++)
                qq[i] = *reinterpret_cast<const uint4*>(
                    g_qh + (size_t)qr[i] * D_DIM + (c + 1) * KC + qs[i] * 8);
        }
        __syncthreads();   // chunk c visible; orders compute(c-1) before buffer reuse

        // ---- compute chunk c: 4 k16 steps
#pragma unroll
        for (int ks = 0; ks < 4; ks++) {
            uint32_t b[2][4];
#pragma unroll
            for (int p = 0; p < 2; p++) {
                uint32_t off = (uint32_t)((wn * 32 + p * 16 + lrow) * 128 + ks * 32 + lhi);
                LDSM_X4_T(b[p][0], b[p][1], b[p][2], b[p][3], sb + mb + SW128(off));
            }
#pragma unroll
            for (int mt = 0; mt < 4; mt++) {
                uint32_t a[4];
                uint32_t off = (uint32_t)((wq * 64 + mt * 16 + lrow) * 128 + ks * 32 + lhi);
                LDSM_X4(a[0], a[1], a[2], a[3], sb + qb + SW128(off));
#pragma unroll
                for (int nt = 0; nt < 4; nt++)
                    MMA_F16(acc[mt][nt], a, b[nt >> 1][nt & 1], b[nt >> 1][(nt & 1) + 2]);
            }
        }
        // no trailing sync: next iteration's STS targets the other buffer.
    }

    // ---- row norms (4 threads/row, fp32 exact)
    sumsq += __shfl_xor_sync(0xFFFFFFFFu, sumsq, 1);
    sumsq += __shfl_xor_sync(0xFFFFFFFFu, sumsq, 2);
    if (mq4 == 0) norms[mrow] = rsqrtf(fmaxf(sumsq, 1e-30f));
    __syncthreads();
    const float* invn = norms;

    // ---- epilogue: per-q-row argmax over this CTA's 128 n
#pragma unroll
    for (int mt = 0; mt < 4; mt++) {
#pragma unroll
        for (int sub = 0; sub < 2; sub++) {
            unsigned long long best = 0ull;
#pragma unroll
            for (int nt = 0; nt < 4; nt++) {
                __half2 h = *reinterpret_cast<__half2*>(&acc[mt][nt][sub]);
                float2 fv = __half22float2(h);
#pragma unroll
                for (int cc = 0; cc < 2; cc++) {
                    int nl = wn * 32 + nt * 8 + 2 * (l & 3) + cc;
                    int n = ntile + nl;
                    if (n < N_MEM) {
                        float s = (cc == 0 ? fv.x : fv.y) * invn[nl];
                        unsigned long long key =
                            ((unsigned long long)fkey(s) << 32) |
                            (unsigned long long)(unsigned int)(~(unsigned int)n);
                        if (key > best) best = key;
                    }
                }
            }
            unsigned long long o;
            o = __shfl_xor_sync(0xFFFFFFFFu, best, 1); if (o > best) best = o;
            o = __shfl_xor_sync(0xFFFFFFFFu, best, 2); if (o > best) best = o;
            if ((l & 3) == 0) {
                int q = wq * 64 + mt * 16 + (l >> 2) + sub * 8;
                atomicMax(&g_best[q], best);
            }
        }
    }
}

// Fused: exact fp32 re-verify of the winner + threshold + decode.
// grid (2, 256), 512 threads. Block handles row b = blockIdx.y,
// outputs j in [blockIdx.x*512, +512).
__global__ __launch_bounds__(512) void final_decode_kernel(const float* __restrict__ Q,
                                                           const float* __restrict__ M,
                                                           const float* __restrict__ W,
                                                           const float* __restrict__ bias,
                                                           float* __restrict__ out) {
    __shared__ float sdq[512], sdm[512], sdp[512];
    __shared__ int s_sel;
    const int b = blockIdx.y;
    const int tid = threadIdx.x;

    unsigned long long pk = g_best[b];
    const int idx = (int)(~(unsigned int)(pk & 0xFFFFFFFFull));

    // exact fp32 cosine of the winner (512 threads x 2 floats)
    const float* q = Q + (size_t)b * D_DIM;
    const float* m = M + (size_t)idx * D_DIM;
    {
        float2 qa = *reinterpret_cast<const float2*>(&q[tid * 2]);
        float2 mb = *reinterpret_cast<const float2*>(&m[tid * 2]);
        sdq[tid] = qa.x * qa.x + qa.y * qa.y;
        sdm[tid] = mb.x * mb.x + mb.y * mb.y;
        sdp[tid] = qa.x * mb.x + qa.y * mb.y;
    }
    __syncthreads();
    for (int s = 256; s > 0; s >>= 1) {
        if (tid < s) {
            sdq[tid] += sdq[tid + s];
            sdm[tid] += sdm[tid + s];
            sdp[tid] += sdp[tid + s];
        }
        __syncthreads();
    }
    if (tid == 0) {
        float sim = sdp[0] / fmaxf(sqrtf(sdq[0]) * sqrtf(sdm[0]), 1e-8f);
        s_sel = (sim > 0.6f) ? idx : -1;
    }
    __syncthreads();

    const int sel = s_sel;
    const int j = blockIdx.x * 512 + tid;
    float r = 0.0f;
    if (sel >= 0) {
        const float* e = M + (size_t)sel * D_DIM;
        const float* w = W + (size_t)j * D_DIM;
        float s = 0.0f;
        for (int k = 0; k < D_DIM; k += 4) {
            float4 ev = *reinterpret_cast<const float4*>(&e[k]);
            float4 wv = *reinterpret_cast<const float4*>(&w[k]);
            s += ev.x * wv.x + ev.y * wv.y + ev.z * wv.z + ev.w * wv.w;
        }
        r = s + bias[j];
    }
    out[(size_t)b * D_DIM + j] = r;
}

extern "C" void kernel_launch(void* const* d_in, const int* in_sizes, int n_in,
                              void* d_out, int out_size) {
    const float* Q    = (const float*)d_in[0];
    const float* M    = (const float*)d_in[1];
    const float* W    = (const float*)d_in[2];
    const float* bias = (const float*)d_in[3];
    float* out = (float*)d_out;

    cudaFuncSetAttribute(simmax_mma, cudaFuncAttributeMaxDynamicSharedMemorySize, SMEM_TOTAL);

    prep_kernel<<<B_Q * D_DIM / 4 / 256, 256>>>(Q);
    simmax_mma<<<NBLK, 512, SMEM_TOTAL>>>(M);
    final_decode_kernel<<<dim3(D_DIM / 512, B_Q), 512>>>(Q, M, W, bias, out);
}